// round 15
// baseline (speedup 1.0000x reference)
#include <cuda_runtime.h>
#include <cuda_fp16.h>
#include <math.h>
#include <stdint.h>

#define N_EMBD 1024
#define NHEAD  16
#define HID    2730
#define FF_LD  2752
#define IW_LD  5504     // interleaved gate/up weight stride = 2*FF_LD
#define BT     4096
#define TS     2048
#define LN_EPS 1e-5f

// ---------------- scratch ---------------------------------------------------
__device__ __half g_hh   [(size_t)BT * N_EMBD];
__device__ __half g_qkvh [(size_t)BT * 3 * N_EMBD];
__device__ __half g_atth [(size_t)BT * N_EMBD];
__device__ __half g_ffh  [(size_t)BT * FF_LD];    // pad cols stay zero (BSS)
__device__ __half g_x2h  [(size_t)BT * N_EMBD];
__device__ __half g_qkvw [(size_t)N_EMBD * 3 * N_EMBD];
__device__ __half g_projw[(size_t)N_EMBD * N_EMBD];
__device__ __half g_downw[(size_t)HID * N_EMBD];
__device__ __half g_wcomb[(size_t)N_EMBD * IW_LD];  // interleaved gate/up, pad zero
__device__ float  g_bcomb[IW_LD];                   // interleaved biases, pad zero

// ---------------- helpers ----------------------------------------------------
__device__ __forceinline__ void cp16(uint32_t dst, const void* src) {
    asm volatile("cp.async.cg.shared.global [%0], [%1], 16;\n" :: "r"(dst), "l"(src));
}
__device__ __forceinline__ void cp16p(uint32_t dst, const void* src, int pb) {
    asm volatile("cp.async.cg.shared.global [%0], [%1], 16, %2;\n" :: "r"(dst), "l"(src), "r"(pb));
}
#define CP_COMMIT() asm volatile("cp.async.commit_group;\n")
#define CP_WAIT1()  asm volatile("cp.async.wait_group 1;\n")

__device__ __forceinline__ float ex2f(float t) {
    float r; asm("ex2.approx.f32 %0, %1;" : "=f"(r) : "f"(t)); return r;
}
__device__ __forceinline__ float rcpf(float t) {
    float r; asm("rcp.approx.f32 %0, %1;" : "=f"(r) : "f"(t)); return r;
}
__device__ __forceinline__ float fsilu(float v) {
    float e = ex2f(-fabsf(v) * 1.4426950408889634f);
    float y = rcpf(1.0f + e);
    float sig = (v >= 0.0f) ? y : (1.0f - y);
    return v * sig;
}

__device__ __forceinline__ void mma16(float* c, const uint32_t* a, uint32_t b0, uint32_t b1) {
    asm volatile(
        "mma.sync.aligned.m16n8k16.row.col.f32.f16.f16.f32 "
        "{%0,%1,%2,%3}, {%4,%5,%6,%7}, {%8,%9}, {%0,%1,%2,%3};\n"
        : "+f"(c[0]), "+f"(c[1]), "+f"(c[2]), "+f"(c[3])
        : "r"(a[0]), "r"(a[1]), "r"(a[2]), "r"(a[3]), "r"(b0), "r"(b1));
}
__device__ __forceinline__ void ldsm4(uint32_t* r, uint32_t addr) {
    asm volatile("ldmatrix.sync.aligned.m8n8.x4.shared.b16 {%0,%1,%2,%3}, [%4];"
        : "=r"(r[0]), "=r"(r[1]), "=r"(r[2]), "=r"(r[3]) : "r"(addr));
}
__device__ __forceinline__ void ldsm4t(uint32_t* r, uint32_t addr) {
    asm volatile("ldmatrix.sync.aligned.m8n8.x4.trans.shared.b16 {%0,%1,%2,%3}, [%4];"
        : "=r"(r[0]), "=r"(r[1]), "=r"(r[2]), "=r"(r[3]) : "r"(addr));
}
__device__ __forceinline__ uint32_t pkh2(float a, float b) {
    __half2 h = __floats2half2_rn(a, b);
    return *(uint32_t*)&h;
}

// ---------------- conversion kernels (split for stream overlap) --------------
__global__ void __launch_bounds__(256) conv_qkvw_kernel(
    const float* __restrict__ qkv_w, __half* __restrict__ qkvw)
{
    int idx = blockIdx.x * 256 + threadIdx.x;   // 786432 quads
    float4 v = ((const float4*)qkv_w)[idx];
    uint2 u; u.x = pkh2(v.x, v.y); u.y = pkh2(v.z, v.w);
    ((uint2*)qkvw)[idx] = u;
}

#define CR_PROJ 1024
#define CR_DOWN (CR_PROJ + 2730)
#define CR_SWI  (CR_DOWN + 11008)
#define CR_ALL  (CR_SWI + 11)

__global__ void __launch_bounds__(256) conv_rest_kernel(
    const float* __restrict__ proj_w, const float* __restrict__ down_w,
    const float* __restrict__ gw, const float* __restrict__ uw,
    const float* __restrict__ gb, const float* __restrict__ ub,
    __half* __restrict__ projw, __half* __restrict__ downw,
    __half* __restrict__ wcomb, float* __restrict__ bcomb)
{
    int b = blockIdx.x, tid = threadIdx.x;
    if (b < CR_PROJ) {
        int idx = b * 256 + tid;
        float4 v = ((const float4*)proj_w)[idx];
        uint2 u; u.x = pkh2(v.x, v.y); u.y = pkh2(v.z, v.w);
        ((uint2*)projw)[idx] = u;
    } else if (b < CR_DOWN) {
        int idx = (b - CR_PROJ) * 256 + tid;
        float4 v = ((const float4*)down_w)[idx];
        uint2 u; u.x = pkh2(v.x, v.y); u.y = pkh2(v.z, v.w);
        ((uint2*)downw)[idx] = u;
    } else if (b < CR_SWI) {
        int idx = (b - CR_DOWN) * 256 + tid;
        int k = idx / FF_LD, j = idx - k * FF_LD;
        if (j < HID) {
            uint32_t v = pkh2(gw[(size_t)k * HID + j], uw[(size_t)k * HID + j]);
            ((uint32_t*)wcomb)[(size_t)k * FF_LD + j] = v;
        }
    } else {
        int j = (b - CR_SWI) * 256 + tid;
        if (j < HID) {
            bcomb[2 * j]     = gb[j];
            bcomb[2 * j + 1] = ub[j];
        }
    }
}

// ---------------- LayerNorm (fp32 or fp16 in, half out) ----------------------
template <int IH>
__global__ void __launch_bounds__(256) ln_kernel(
    const void* __restrict__ xv, const float* __restrict__ g,
    const float* __restrict__ b, __half* __restrict__ out)
{
    int row = blockIdx.x;
    int tid = threadIdx.x;
    float4 v;
    if (IH) {
        uint2 u = ((const uint2*)((const __half*)xv + (size_t)row * N_EMBD))[tid];
        float2 a = __half22float2(*(__half2*)&u.x);
        float2 c = __half22float2(*(__half2*)&u.y);
        v = make_float4(a.x, a.y, c.x, c.y);
    } else {
        v = ((const float4*)((const float*)xv + (size_t)row * N_EMBD))[tid];
    }
    float s  = v.x + v.y + v.z + v.w;
    float ss = v.x*v.x + v.y*v.y + v.z*v.z + v.w*v.w;
    #pragma unroll
    for (int o = 16; o; o >>= 1) {
        s  += __shfl_xor_sync(0xffffffffu, s, o);
        ss += __shfl_xor_sync(0xffffffffu, ss, o);
    }
    __shared__ float red[16];
    int warp = tid >> 5, lane = tid & 31;
    if (lane == 0) { red[warp] = s; red[8 + warp] = ss; }
    __syncthreads();
    if (tid == 0) {
        float a = 0.f, a2 = 0.f;
        #pragma unroll
        for (int i = 0; i < 8; i++) { a += red[i]; a2 += red[8 + i]; }
        red[0] = a; red[8] = a2;
    }
    __syncthreads();
    float mean = red[0] * (1.0f / N_EMBD);
    float var  = red[8] * (1.0f / N_EMBD) - mean * mean;
    float rstd = rsqrtf(var + LN_EPS);
    float4 go = ((const float4*)g)[tid];
    float4 bo = ((const float4*)b)[tid];
    uint2 u;
    u.x = pkh2((v.x - mean) * rstd * go.x + bo.x, (v.y - mean) * rstd * go.y + bo.y);
    u.y = pkh2((v.z - mean) * rstd * go.z + bo.z, (v.w - mean) * rstd * go.w + bo.w);
    ((uint2*)(out + (size_t)row * N_EMBD))[tid] = u;
}

// ---------------- FP16 GEMM: 2-stage pipeline, raw mma, register epilogue ----
#define H_ALD 72
#define H_BLD 136
#define H_AST (128 * H_ALD)
#define H_BST (64 * H_BLD)
#define GSMEM ((2 * H_AST + 2 * H_BST) * 2)

enum { EPI_BIAS = 0, EPI_RES = 1, EPI_SWIGLU = 2 };

template <int EPI, int OH, int EH>
__global__ void __launch_bounds__(256, 2) gemm_fp16(
    const __half* __restrict__ A, const __half* __restrict__ B,
    const float* __restrict__ bias, const void* __restrict__ extra,
    void* __restrict__ Cv, int N, int K, int lda, int ldb, int ldc)
{
    extern __shared__ __align__(16) char smc[];
    __half* As = (__half*)smc;
    __half* Bs = As + 2 * H_AST;
    uint32_t sA = (uint32_t)__cvta_generic_to_shared(As);
    uint32_t sB = (uint32_t)__cvta_generic_to_shared(Bs);

    int tid = threadIdx.x;
    int warp = tid >> 5, lane = tid & 31;
    int gid = lane >> 2, tig = lane & 3;

    int gx = gridDim.x, gy = gridDim.y;
    int bid = blockIdx.y * gx + blockIdx.x;
    const int G = 8;
    int band_sz = G * gx;
    int band = bid / band_sz;
    int rem = bid - band * band_sz;
    int rows = gy - band * G; if (rows > G) rows = G;
    int byi = band * G + rem % rows;
    int bxi = rem / rows;
    int bm = byi * 128, bn = bxi * 128;

    int wm = (warp >> 2) * 64, wn = (warp & 3) * 32;
    int nkt = (K + 63) >> 6;

    float acc[4][4][4];
    #pragma unroll
    for (int m = 0; m < 4; m++)
        #pragma unroll
        for (int n = 0; n < 4; n++)
            #pragma unroll
            for (int e = 0; e < 4; e++) acc[m][n][e] = 0.0f;

    int l8 = lane & 7, quad = lane >> 3;
    int mrow = (quad & 1) * 8 + l8;
    int mcol = (quad >> 1) * 8;
    uint32_t aoff[4], boff[2];
    #pragma unroll
    for (int m = 0; m < 4; m++)
        aoff[m] = (uint32_t)(((wm + m * 16 + mrow) * H_ALD + mcol) * 2);
    #pragma unroll
    for (int p = 0; p < 2; p++)
        boff[p] = (uint32_t)((mrow * H_BLD + wn + p * 16 + mcol) * 2);

    auto loadT = [&](int kt) {
        int stg = kt & 1;
        int k0 = kt << 6;
        #pragma unroll
        for (int j = 0; j < 4; j++) {
            int idx = tid + j * 256;
            int r = idx >> 3, c8 = (idx & 7) << 3;
            uint32_t dst = sA + (uint32_t)(stg * H_AST + r * H_ALD + c8) * 2u;
            cp16(dst, A + (size_t)(bm + r) * lda + k0 + c8);
        }
        #pragma unroll
        for (int j = 0; j < 4; j++) {
            int idx = tid + j * 256;
            int r = idx >> 4, c8 = (idx & 15) << 3;
            int kk = k0 + r;
            int pb = (kk < K) ? 16 : 0;
            uint32_t dst = sB + (uint32_t)(stg * H_BST + r * H_BLD + c8) * 2u;
            cp16p(dst, B + (size_t)kk * ldb + bn + c8, pb);
        }
    };

    loadT(0);
    CP_COMMIT();
    for (int kt = 0; kt < nkt; kt++) {
        if (kt + 1 < nkt) loadT(kt + 1);
        CP_COMMIT();
        CP_WAIT1();
        __syncthreads();
        uint32_t aBase = sA + (uint32_t)((kt & 1) * H_AST) * 2u;
        uint32_t bBase = sB + (uint32_t)((kt & 1) * H_BST) * 2u;
        #pragma unroll
        for (int ks = 0; ks < 4; ks++) {
            uint32_t a[4][4], bb[2][4];
            #pragma unroll
            for (int m = 0; m < 4; m++)
                ldsm4(a[m], aBase + aoff[m] + (uint32_t)(ks * 32));
            #pragma unroll
            for (int p = 0; p < 2; p++)
                ldsm4t(bb[p], bBase + boff[p] + (uint32_t)(ks * 16 * H_BLD * 2));
            #pragma unroll
            for (int m = 0; m < 4; m++) {
                #pragma unroll
                for (int p = 0; p < 2; p++) {
                    mma16(acc[m][p * 2],     a[m], bb[p][0], bb[p][1]);
                    mma16(acc[m][p * 2 + 1], a[m], bb[p][2], bb[p][3]);
                }
            }
        }
        __syncthreads();
    }

    #pragma unroll
    for (int m = 0; m < 4; m++) {
        int gr = bm + wm + m * 16 + gid;
        #pragma unroll
        for (int n = 0; n < 4; n++) {
            int gc = bn + wn + n * 8 + 2 * tig;
            if (gc < N) {
                float2 bi = *(const float2*)&bias[gc];
                float v0 = acc[m][n][0] + bi.x;
                float v1 = acc[m][n][1] + bi.y;
                float v2 = acc[m][n][2] + bi.x;
                float v3 = acc[m][n][3] + bi.y;
                if (EPI == EPI_SWIGLU) {
                    __half* C = (__half*)Cv;
                    int jcol = gc >> 1;
                    C[(size_t)gr * ldc + jcol]       = __float2half(fsilu(v0) * v1);
                    C[(size_t)(gr + 8) * ldc + jcol] = __float2half(fsilu(v2) * v3);
                } else {
                    if (EPI == EPI_RES) {
                        if (EH) {
                            const __half* ex = (const __half*)extra;
                            float2 e0 = __half22float2(*(const __half2*)&ex[(size_t)gr * ldc + gc]);
                            float2 e1 = __half22float2(*(const __half2*)&ex[(size_t)(gr + 8) * ldc + gc]);
                            v0 += e0.x; v1 += e0.y; v2 += e1.x; v3 += e1.y;
                        } else {
                            const float* ex = (const float*)extra;
                            float2 e0 = *(const float2*)&ex[(size_t)gr * ldc + gc];
                            float2 e1 = *(const float2*)&ex[(size_t)(gr + 8) * ldc + gc];
                            v0 += e0.x; v1 += e0.y; v2 += e1.x; v3 += e1.y;
                        }
                    }
                    if (OH) {
                        __half* C = (__half*)Cv;
                        *(uint32_t*)&C[(size_t)gr * ldc + gc]       = pkh2(v0, v1);
                        *(uint32_t*)&C[(size_t)(gr + 8) * ldc + gc] = pkh2(v2, v3);
                    } else {
                        float* C = (float*)Cv;
                        *(float2*)&C[(size_t)gr * ldc + gc]       = make_float2(v0, v1);
                        *(float2*)&C[(size_t)(gr + 8) * ldc + gc] = make_float2(v2, v3);
                    }
                }
            }
        }
    }
}

// ---------------- Flash attention: reverse kv order, vote-skip rescale -------
#define AKLD 72
#define AK_ST (128 * AKLD)
#define ASMEM ((4 * AK_ST) * 2)

__global__ void __launch_bounds__(256) attn_kernel(
    const __half* __restrict__ qkv, __half* __restrict__ out)
{
    extern __shared__ __align__(16) char smc[];
    __half* Ks = (__half*)smc;
    uint32_t sK = (uint32_t)__cvta_generic_to_shared(Ks);
    uint32_t sV = sK + (uint32_t)(2 * AK_ST) * 2u;

    int tid = threadIdx.x, lane = tid & 31, warp = tid >> 5;
    int gid = lane >> 2, tig = lane & 3;
    int qt = 15 - blockIdx.x;
    int h  = blockIdx.y, bb = blockIdx.z;
    int q0 = qt * 128;
    int R  = warp * 16;
    const float LOG2E = 1.4426950408889634f;
    float qscale = 0.125f * LOG2E;
    float slope  = exp2f(-0.5f * (float)(h + 1)) * LOG2E;
    size_t base = (size_t)bb * TS * 3072;
    const __half* Qg = qkv + base + h * 64;
    const __half* Kg = Qg + 1024;
    const __half* Vg = Qg + 2048;

    int nsb = qt + 1;

    auto loadKV = [&](int sb) {
        int stg = sb & 1, k0 = sb * 128;
        #pragma unroll
        for (int j = 0; j < 4; j++) {
            int idx = tid + j * 256;
            int r = idx >> 3, c8 = (idx & 7) << 3;
            size_t go = (size_t)(k0 + r) * 3072 + c8;
            cp16(sK + (uint32_t)(stg * AK_ST + r * AKLD + c8) * 2u, Kg + go);
            cp16(sV + (uint32_t)(stg * AK_ST + r * AKLD + c8) * 2u, Vg + go);
        }
    };

    loadKV(nsb - 1);
    CP_COMMIT();

    uint32_t qa[4][4];
    {
        const __half* Qr1 = Qg + (size_t)(q0 + R + gid) * 3072;
        const __half* Qr2 = Qr1 + 8 * 3072;
        #pragma unroll
        for (int kt = 0; kt < 4; kt++) {
            int d0 = kt * 16 + 2 * tig;
            qa[kt][0] = pkh2(__half2float(Qr1[d0]) * qscale, __half2float(Qr1[d0 + 1]) * qscale);
            qa[kt][1] = pkh2(__half2float(Qr2[d0]) * qscale, __half2float(Qr2[d0 + 1]) * qscale);
            qa[kt][2] = pkh2(__half2float(Qr1[d0 + 8]) * qscale, __half2float(Qr1[d0 + 9]) * qscale);
            qa[kt][3] = pkh2(__half2float(Qr2[d0 + 8]) * qscale, __half2float(Qr2[d0 + 9]) * qscale);
        }
    }

    float oa[8][4];
    #pragma unroll
    for (int nt = 0; nt < 8; nt++)
        #pragma unroll
        for (int e = 0; e < 4; e++) oa[nt][e] = 0.0f;
    float m1 = -1e30f, m2 = -1e30f;
    float lp1 = 0.0f, lp2 = 0.0f;

    int qp1 = q0 + R + gid, qp2 = qp1 + 8;

    uint32_t koff = (uint32_t)(((((lane >> 4) << 3) + (lane & 7)) * AKLD + (((lane >> 3) & 1) << 3)) * 2);
    uint32_t voff = (uint32_t)(((lane & 15) * AKLD + (((lane >> 4) & 1) << 3)) * 2);

    for (int i = 0; i < nsb; i++) {
        int sb = nsb - 1 - i;
        if (sb > 0) loadKV(sb - 1);
        CP_COMMIT();
        CP_WAIT1();
        __syncthreads();
        uint32_t sKst = sK + (uint32_t)((sb & 1) * AK_ST) * 2u;
        uint32_t sVst = sV + (uint32_t)((sb & 1) * AK_ST) * 2u;

        #pragma unroll
        for (int hf = 0; hf < 2; hf++) {
            int half = 1 - hf;
            int k0 = sb * 128 + half * 64;
            uint32_t sKcur = sKst + (uint32_t)(half * 64 * AKLD) * 2u;
            uint32_t sVcur = sVst + (uint32_t)(half * 64 * AKLD) * 2u;
            int vis = q0 + R + 15 - k0;

            if (vis >= 0) {
                int ntmax = vis >> 3;
                ntmax = (ntmax >= 7) ? 8 : (ntmax + 1);
                float sacc[8][4];
                #pragma unroll
                for (int nt = 0; nt < 8; nt++)
                    #pragma unroll
                    for (int e = 0; e < 4; e++) sacc[nt][e] = 0.0f;
                #pragma unroll
                for (int ntp = 0; ntp < 8; ntp += 2) {
                    if (ntp < ntmax) {
                        #pragma unroll
                        for (int kt = 0; kt < 4; kt++) {
                            uint32_t bbr[4];
                            ldsm4(bbr, sKcur + koff + (uint32_t)((ntp * 8 * AKLD + kt * 16) * 2));
                            mma16(sacc[ntp],     qa[kt], bbr[0], bbr[1]);
                            mma16(sacc[ntp + 1], qa[kt], bbr[2], bbr[3]);
                        }
                    }
                }
                bool domask = (k0 + 63 > q0 + R);
                float mx1 = -1e30f, mx2 = -1e30f;
                #pragma unroll
                for (int nt = 0; nt < 8; nt++) {
                    if (nt >= ntmax) continue;
                    int kp0 = k0 + nt * 8 + tig * 2;
                    float cbA = -slope * (float)kp0;
                    float cbB = cbA - slope;
                    float s0 = sacc[nt][0] + cbA;
                    float s1 = sacc[nt][1] + cbB;
                    float s2 = sacc[nt][2] + cbA;
                    float s3 = sacc[nt][3] + cbB;
                    if (domask) {
                        if (kp0     > qp1) s0 = -1e30f;
                        if (kp0 + 1 > qp1) s1 = -1e30f;
                        if (kp0     > qp2) s2 = -1e30f;
                        if (kp0 + 1 > qp2) s3 = -1e30f;
                    }
                    sacc[nt][0] = s0; sacc[nt][1] = s1; sacc[nt][2] = s2; sacc[nt][3] = s3;
                    mx1 = fmaxf(mx1, fmaxf(s0, s1));
                    mx2 = fmaxf(mx2, fmaxf(s2, s3));
                }
                mx1 = fmaxf(mx1, __shfl_xor_sync(0xffffffffu, mx1, 1));
                mx1 = fmaxf(mx1, __shfl_xor_sync(0xffffffffu, mx1, 2));
                mx2 = fmaxf(mx2, __shfl_xor_sync(0xffffffffu, mx2, 1));
                mx2 = fmaxf(mx2, __shfl_xor_sync(0xffffffffu, mx2, 2));
                bool upd = (mx1 > m1) || (mx2 > m2);
                if (__any_sync(0xffffffffu, upd)) {
                    float mn1 = fmaxf(m1, mx1), mn2 = fmaxf(m2, mx2);
                    float f1 = ex2f(m1 - mn1), f2 = ex2f(m2 - mn2);
                    lp1 *= f1;  lp2 *= f2;
                    #pragma unroll
                    for (int nt = 0; nt < 8; nt++) {
                        oa[nt][0] *= f1; oa[nt][1] *= f1;
                        oa[nt][2] *= f2; oa[nt][3] *= f2;
                    }
                    m1 = mn1;  m2 = mn2;
                }
                #pragma unroll
                for (int nt = 0; nt < 8; nt++) {
                    if (nt >= ntmax) continue;
                    float p0 = ex2f(sacc[nt][0] - m1);
                    float p1 = ex2f(sacc[nt][1] - m1);
                    float p2 = ex2f(sacc[nt][2] - m2);
                    float p3 = ex2f(sacc[nt][3] - m2);
                    sacc[nt][0] = p0; sacc[nt][1] = p1; sacc[nt][2] = p2; sacc[nt][3] = p3;
                    lp1 += p0 + p1; lp2 += p2 + p3;
                }
                int jmax = (ntmax + 1) >> 1;
                #pragma unroll
                for (int j = 0; j < 4; j++) {
                    if (j >= jmax) continue;
                    uint32_t pa[4];
                    pa[0] = pkh2(sacc[2*j][0], sacc[2*j][1]);
                    pa[1] = pkh2(sacc[2*j][2], sacc[2*j][3]);
                    if (2*j + 1 < ntmax) {
                        pa[2] = pkh2(sacc[2*j+1][0], sacc[2*j+1][1]);
                        pa[3] = pkh2(sacc[2*j+1][2], sacc[2*j+1][3]);
                    } else { pa[2] = 0u; pa[3] = 0u; }
                    uint32_t rowa = sVcur + voff + (uint32_t)(j * 16 * AKLD) * 2u;
                    #pragma unroll
                    for (int nt = 0; nt < 8; nt += 2) {
                        uint32_t bbr[4];
                        ldsm4t(bbr, rowa + (uint32_t)(nt * 8) * 2u);
                        mma16(oa[nt],     pa, bbr[0], bbr[1]);
                        mma16(oa[nt + 1], pa, bbr[2], bbr[3]);
                    }
                }
            }
        }
        __syncthreads();
    }

    lp1 += __shfl_xor_sync(0xffffffffu, lp1, 1);
    lp1 += __shfl_xor_sync(0xffffffffu, lp1, 2);
    lp2 += __shfl_xor_sync(0xffffffffu, lp2, 1);
    lp2 += __shfl_xor_sync(0xffffffffu, lp2, 2);
    float il1 = rcpf(lp1), il2 = rcpf(lp2);
    __half* Or1 = out + (size_t)(bb * TS + q0 + R + gid) * N_EMBD + h * 64;
    __half* Or2 = Or1 + 8 * N_EMBD;
    #pragma unroll
    for (int nt = 0; nt < 8; nt++) {
        *(uint32_t*)&Or1[nt * 8 + 2 * tig] = pkh2(oa[nt][0] * il1, oa[nt][1] * il1);
        *(uint32_t*)&Or2[nt * 8 + 2 * tig] = pkh2(oa[nt][2] * il2, oa[nt][3] * il2);
    }
}

// ---------------- launch -----------------------------------------------------
extern "C" void kernel_launch(void* const* d_in, const int* in_sizes, int n_in,
                              void* d_out, int out_size)
{
    (void)in_sizes; (void)n_in; (void)out_size;
    const float* x      = (const float*)d_in[0];
    const float* ln1_g  = (const float*)d_in[1];
    const float* ln1_b  = (const float*)d_in[2];
    const float* qkv_w  = (const float*)d_in[3];
    const float* qkv_b  = (const float*)d_in[4];
    const float* proj_w = (const float*)d_in[5];
    const float* proj_b = (const float*)d_in[6];
    const float* ln2_g  = (const float*)d_in[7];
    const float* ln2_b  = (const float*)d_in[8];
    const float* gate_w = (const float*)d_in[9];
    const float* gate_b = (const float*)d_in[10];
    const float* up_w   = (const float*)d_in[11];
    const float* up_b   = (const float*)d_in[12];
    const float* down_w = (const float*)d_in[13];
    const float* down_b = (const float*)d_in[14];
    float* out = (float*)d_out;

    __half *hh, *qkvh, *atth, *ffh, *x2h, *qkvw, *projw, *downw, *wcomb;
    float *bcomb;
    cudaGetSymbolAddress((void**)&hh,    g_hh);
    cudaGetSymbolAddress((void**)&qkvh,  g_qkvh);
    cudaGetSymbolAddress((void**)&atth,  g_atth);
    cudaGetSymbolAddress((void**)&ffh,   g_ffh);
    cudaGetSymbolAddress((void**)&x2h,   g_x2h);
    cudaGetSymbolAddress((void**)&qkvw,  g_qkvw);
    cudaGetSymbolAddress((void**)&projw, g_projw);
    cudaGetSymbolAddress((void**)&downw, g_downw);
    cudaGetSymbolAddress((void**)&wcomb, g_wcomb);
    cudaGetSymbolAddress((void**)&bcomb, g_bcomb);

    cudaFuncSetAttribute(gemm_fp16<EPI_BIAS,  1,0>, cudaFuncAttributeMaxDynamicSharedMemorySize, GSMEM);
    cudaFuncSetAttribute(gemm_fp16<EPI_RES,   1,0>, cudaFuncAttributeMaxDynamicSharedMemorySize, GSMEM);
    cudaFuncSetAttribute(gemm_fp16<EPI_RES,   0,1>, cudaFuncAttributeMaxDynamicSharedMemorySize, GSMEM);
    cudaFuncSetAttribute(gemm_fp16<EPI_SWIGLU,1,0>, cudaFuncAttributeMaxDynamicSharedMemorySize, GSMEM);
    cudaFuncSetAttribute(attn_kernel, cudaFuncAttributeMaxDynamicSharedMemorySize, ASMEM);

    // lazy side stream + events (created on the uncaptured correctness call)
    static cudaStream_t s2 = nullptr;
    static cudaEvent_t evStart = nullptr, evLN = nullptr, evRest = nullptr;
    if (!s2) {
        cudaStreamCreateWithFlags(&s2, cudaStreamNonBlocking);
        cudaEventCreateWithFlags(&evStart, cudaEventDisableTiming);
        cudaEventCreateWithFlags(&evLN,    cudaEventDisableTiming);
        cudaEventCreateWithFlags(&evRest,  cudaEventDisableTiming);
    }
    cudaStream_t s0 = 0;  // capture (legacy default) stream

    // fork side stream
    cudaEventRecord(evStart, s0);
    cudaStreamWaitEvent(s2, evStart, 0);

    // side stream: LN1, then remaining weight conversions (overlap with main)
    ln_kernel<0><<<BT, 256, 0, s2>>>(x, ln1_g, ln1_b, hh);
    cudaEventRecord(evLN, s2);
    conv_rest_kernel<<<CR_ALL, 256, 0, s2>>>(proj_w, down_w, gate_w, up_w, gate_b, up_b,
                                             projw, downw, wcomb, bcomb);
    cudaEventRecord(evRest, s2);

    // main stream: qkv weight conversion (overlaps LN1)
    conv_qkvw_kernel<<<3072, 256, 0, s0>>>(qkv_w, qkvw);
    cudaStreamWaitEvent(s0, evLN, 0);

    // 2) qkv
    {
        dim3 g(3 * N_EMBD / 128, BT / 128);
        gemm_fp16<EPI_BIAS,1,0><<<g, 256, GSMEM, s0>>>(hh, qkvw, qkv_b, nullptr, qkvh,
                                                       3 * N_EMBD, N_EMBD, N_EMBD, 3 * N_EMBD, 3 * N_EMBD);
    }
    // 3) attention (conv_rest overlaps underneath)
    {
        dim3 g(TS / 128, NHEAD, 2);
        attn_kernel<<<g, 256, ASMEM, s0>>>(qkvh, atth);
    }
    // join: proj/down/swiglu weights ready
    cudaStreamWaitEvent(s0, evRest, 0);

    // 4) x2 = att @ proj_w + b + x   (half out)
    {
        dim3 g(N_EMBD / 128, BT / 128);
        gemm_fp16<EPI_RES,1,0><<<g, 256, GSMEM, s0>>>(atth, projw, proj_b, x, x2h,
                                                      N_EMBD, N_EMBD, N_EMBD, N_EMBD, N_EMBD);
    }
    // 5) LN2 (fp16 in)
    ln_kernel<1><<<BT, 256, 0, s0>>>(x2h, ln2_g, ln2_b, hh);
    // 6+7) ff = silu(h@gate_w+bg) * (h@up_w+bu)
    {
        dim3 g(IW_LD / 128, BT / 128);
        gemm_fp16<EPI_SWIGLU,1,0><<<g, 256, GSMEM, s0>>>(hh, wcomb, bcomb, nullptr, ffh,
                                                         2 * HID, N_EMBD, N_EMBD, IW_LD, FF_LD);
    }
    // 8) out = ff @ down_w + b + x2  (residual half, out fp32)
    {
        dim3 g(N_EMBD / 128, BT / 128);
        gemm_fp16<EPI_RES,0,1><<<g, 256, GSMEM, s0>>>(ffh, downw, down_b, x2h, out,
                                                      N_EMBD, HID, FF_LD, N_EMBD, N_EMBD);
    }
}

// round 16
// speedup vs baseline: 1.0938x; 1.0938x over previous
#include <cuda_runtime.h>
#include <cuda_fp16.h>
#include <math.h>
#include <stdint.h>

#define N_EMBD 1024
#define NHEAD  16
#define HID    2730
#define FF_LD  2752
#define IW_LD  5504     // interleaved gate/up weight stride = 2*FF_LD
#define BT     4096
#define TS     2048
#define LN_EPS 1e-5f

// ---------------- scratch ---------------------------------------------------
__device__ __half g_hh   [(size_t)BT * N_EMBD];
__device__ __half g_qkvh [(size_t)BT * 3 * N_EMBD];
__device__ __half g_atth [(size_t)BT * N_EMBD];
__device__ __half g_ffh  [(size_t)BT * FF_LD];    // pad cols stay zero (BSS)
__device__ __half g_x2h  [(size_t)BT * N_EMBD];
__device__ __half g_qkvw [(size_t)N_EMBD * 3 * N_EMBD];
__device__ __half g_projw[(size_t)N_EMBD * N_EMBD];
__device__ __half g_downw[(size_t)HID * N_EMBD];
__device__ __half g_wcomb[(size_t)N_EMBD * IW_LD];  // interleaved gate/up, pad zero
__device__ float  g_bcomb[IW_LD];                   // interleaved biases, pad zero

// ---------------- helpers ----------------------------------------------------
__device__ __forceinline__ void cp16(uint32_t dst, const void* src) {
    asm volatile("cp.async.cg.shared.global [%0], [%1], 16;\n" :: "r"(dst), "l"(src));
}
__device__ __forceinline__ void cp16p(uint32_t dst, const void* src, int pb) {
    asm volatile("cp.async.cg.shared.global [%0], [%1], 16, %2;\n" :: "r"(dst), "l"(src), "r"(pb));
}
#define CP_COMMIT() asm volatile("cp.async.commit_group;\n")
#define CP_WAIT1()  asm volatile("cp.async.wait_group 1;\n")

__device__ __forceinline__ float ex2f(float t) {
    float r; asm("ex2.approx.f32 %0, %1;" : "=f"(r) : "f"(t)); return r;
}
__device__ __forceinline__ float rcpf(float t) {
    float r; asm("rcp.approx.f32 %0, %1;" : "=f"(r) : "f"(t)); return r;
}
__device__ __forceinline__ float fsilu(float v) {
    float e = ex2f(-fabsf(v) * 1.4426950408889634f);
    float y = rcpf(1.0f + e);
    float sig = (v >= 0.0f) ? y : (1.0f - y);
    return v * sig;
}

__device__ __forceinline__ void mma16(float* c, const uint32_t* a, uint32_t b0, uint32_t b1) {
    asm volatile(
        "mma.sync.aligned.m16n8k16.row.col.f32.f16.f16.f32 "
        "{%0,%1,%2,%3}, {%4,%5,%6,%7}, {%8,%9}, {%0,%1,%2,%3};\n"
        : "+f"(c[0]), "+f"(c[1]), "+f"(c[2]), "+f"(c[3])
        : "r"(a[0]), "r"(a[1]), "r"(a[2]), "r"(a[3]), "r"(b0), "r"(b1));
}
__device__ __forceinline__ void ldsm4(uint32_t* r, uint32_t addr) {
    asm volatile("ldmatrix.sync.aligned.m8n8.x4.shared.b16 {%0,%1,%2,%3}, [%4];"
        : "=r"(r[0]), "=r"(r[1]), "=r"(r[2]), "=r"(r[3]) : "r"(addr));
}
__device__ __forceinline__ void ldsm4t(uint32_t* r, uint32_t addr) {
    asm volatile("ldmatrix.sync.aligned.m8n8.x4.trans.shared.b16 {%0,%1,%2,%3}, [%4];"
        : "=r"(r[0]), "=r"(r[1]), "=r"(r[2]), "=r"(r[3]) : "r"(addr));
}
__device__ __forceinline__ uint32_t pkh2(float a, float b) {
    __half2 h = __floats2half2_rn(a, b);
    return *(uint32_t*)&h;
}

// ---------------- merged conversion kernel (ONE launch) ----------------------
#define CB_QKV  3072
#define CB_PROJ (CB_QKV + 1024)
#define CB_DOWN (CB_PROJ + 2730)
#define CB_SWI  (CB_DOWN + 11008)
#define CB_ALL  (CB_SWI + 11)

__global__ void __launch_bounds__(256) convall_kernel(
    const float* __restrict__ qkv_w, const float* __restrict__ proj_w,
    const float* __restrict__ down_w, const float* __restrict__ gw,
    const float* __restrict__ uw, const float* __restrict__ gb,
    const float* __restrict__ ub,
    __half* __restrict__ qkvw, __half* __restrict__ projw,
    __half* __restrict__ downw, __half* __restrict__ wcomb,
    float* __restrict__ bcomb)
{
    int b = blockIdx.x, tid = threadIdx.x;
    if (b < CB_QKV) {
        int idx = b * 256 + tid;
        float4 v = ((const float4*)qkv_w)[idx];
        uint2 u; u.x = pkh2(v.x, v.y); u.y = pkh2(v.z, v.w);
        ((uint2*)qkvw)[idx] = u;
    } else if (b < CB_PROJ) {
        int idx = (b - CB_QKV) * 256 + tid;
        float4 v = ((const float4*)proj_w)[idx];
        uint2 u; u.x = pkh2(v.x, v.y); u.y = pkh2(v.z, v.w);
        ((uint2*)projw)[idx] = u;
    } else if (b < CB_DOWN) {
        int idx = (b - CB_PROJ) * 256 + tid;
        float4 v = ((const float4*)down_w)[idx];
        uint2 u; u.x = pkh2(v.x, v.y); u.y = pkh2(v.z, v.w);
        ((uint2*)downw)[idx] = u;
    } else if (b < CB_SWI) {
        int idx = (b - CB_DOWN) * 256 + tid;
        int k = idx / FF_LD, j = idx - k * FF_LD;
        if (j < HID) {
            uint32_t v = pkh2(gw[(size_t)k * HID + j], uw[(size_t)k * HID + j]);
            ((uint32_t*)wcomb)[(size_t)k * FF_LD + j] = v;
        }
    } else {
        int j = (b - CB_SWI) * 256 + tid;
        if (j < HID) {
            bcomb[2 * j]     = gb[j];
            bcomb[2 * j + 1] = ub[j];
        }
    }
}

// ---------------- LayerNorm (fp32 or fp16 in, half out) ----------------------
template <int IH>
__global__ void __launch_bounds__(256) ln_kernel(
    const void* __restrict__ xv, const float* __restrict__ g,
    const float* __restrict__ b, __half* __restrict__ out)
{
    int row = blockIdx.x;
    int tid = threadIdx.x;
    float4 v;
    if (IH) {
        uint2 u = ((const uint2*)((const __half*)xv + (size_t)row * N_EMBD))[tid];
        float2 a = __half22float2(*(__half2*)&u.x);
        float2 c = __half22float2(*(__half2*)&u.y);
        v = make_float4(a.x, a.y, c.x, c.y);
    } else {
        v = ((const float4*)((const float*)xv + (size_t)row * N_EMBD))[tid];
    }
    float s  = v.x + v.y + v.z + v.w;
    float ss = v.x*v.x + v.y*v.y + v.z*v.z + v.w*v.w;
    #pragma unroll
    for (int o = 16; o; o >>= 1) {
        s  += __shfl_xor_sync(0xffffffffu, s, o);
        ss += __shfl_xor_sync(0xffffffffu, ss, o);
    }
    __shared__ float red[16];
    int warp = tid >> 5, lane = tid & 31;
    if (lane == 0) { red[warp] = s; red[8 + warp] = ss; }
    __syncthreads();
    if (tid == 0) {
        float a = 0.f, a2 = 0.f;
        #pragma unroll
        for (int i = 0; i < 8; i++) { a += red[i]; a2 += red[8 + i]; }
        red[0] = a; red[8] = a2;
    }
    __syncthreads();
    float mean = red[0] * (1.0f / N_EMBD);
    float var  = red[8] * (1.0f / N_EMBD) - mean * mean;
    float rstd = rsqrtf(var + LN_EPS);
    float4 go = ((const float4*)g)[tid];
    float4 bo = ((const float4*)b)[tid];
    uint2 u;
    u.x = pkh2((v.x - mean) * rstd * go.x + bo.x, (v.y - mean) * rstd * go.y + bo.y);
    u.y = pkh2((v.z - mean) * rstd * go.z + bo.z, (v.w - mean) * rstd * go.w + bo.w);
    ((uint2*)(out + (size_t)row * N_EMBD))[tid] = u;
}

// ---------------- FP16 GEMM: 2-stage pipeline, raw mma, register epilogue ----
#define H_ALD 72
#define H_BLD 136
#define H_AST (128 * H_ALD)
#define H_BST (64 * H_BLD)
#define GSMEM ((2 * H_AST + 2 * H_BST) * 2)

enum { EPI_BIAS = 0, EPI_RES = 1, EPI_SWIGLU = 2 };

template <int EPI, int OH, int EH>
__global__ void __launch_bounds__(256, 2) gemm_fp16(
    const __half* __restrict__ A, const __half* __restrict__ B,
    const float* __restrict__ bias, const void* __restrict__ extra,
    void* __restrict__ Cv, int N, int K, int lda, int ldb, int ldc)
{
    extern __shared__ __align__(16) char smc[];
    __half* As = (__half*)smc;
    __half* Bs = As + 2 * H_AST;
    uint32_t sA = (uint32_t)__cvta_generic_to_shared(As);
    uint32_t sB = (uint32_t)__cvta_generic_to_shared(Bs);

    int tid = threadIdx.x;
    int warp = tid >> 5, lane = tid & 31;
    int gid = lane >> 2, tig = lane & 3;

    int gx = gridDim.x, gy = gridDim.y;
    int bid = blockIdx.y * gx + blockIdx.x;
    const int G = 8;
    int band_sz = G * gx;
    int band = bid / band_sz;
    int rem = bid - band * band_sz;
    int rows = gy - band * G; if (rows > G) rows = G;
    int byi = band * G + rem % rows;
    int bxi = rem / rows;
    int bm = byi * 128, bn = bxi * 128;

    int wm = (warp >> 2) * 64, wn = (warp & 3) * 32;
    int nkt = (K + 63) >> 6;

    float acc[4][4][4];
    #pragma unroll
    for (int m = 0; m < 4; m++)
        #pragma unroll
        for (int n = 0; n < 4; n++)
            #pragma unroll
            for (int e = 0; e < 4; e++) acc[m][n][e] = 0.0f;

    int l8 = lane & 7, quad = lane >> 3;
    int mrow = (quad & 1) * 8 + l8;
    int mcol = (quad >> 1) * 8;
    uint32_t aoff[4], boff[2];
    #pragma unroll
    for (int m = 0; m < 4; m++)
        aoff[m] = (uint32_t)(((wm + m * 16 + mrow) * H_ALD + mcol) * 2);
    #pragma unroll
    for (int p = 0; p < 2; p++)
        boff[p] = (uint32_t)((mrow * H_BLD + wn + p * 16 + mcol) * 2);

    auto loadT = [&](int kt) {
        int stg = kt & 1;
        int k0 = kt << 6;
        #pragma unroll
        for (int j = 0; j < 4; j++) {
            int idx = tid + j * 256;
            int r = idx >> 3, c8 = (idx & 7) << 3;
            uint32_t dst = sA + (uint32_t)(stg * H_AST + r * H_ALD + c8) * 2u;
            cp16(dst, A + (size_t)(bm + r) * lda + k0 + c8);
        }
        #pragma unroll
        for (int j = 0; j < 4; j++) {
            int idx = tid + j * 256;
            int r = idx >> 4, c8 = (idx & 15) << 3;
            int kk = k0 + r;
            int pb = (kk < K) ? 16 : 0;
            uint32_t dst = sB + (uint32_t)(stg * H_BST + r * H_BLD + c8) * 2u;
            cp16p(dst, B + (size_t)kk * ldb + bn + c8, pb);
        }
    };

    loadT(0);
    CP_COMMIT();
    for (int kt = 0; kt < nkt; kt++) {
        if (kt + 1 < nkt) loadT(kt + 1);
        CP_COMMIT();
        CP_WAIT1();
        __syncthreads();
        uint32_t aBase = sA + (uint32_t)((kt & 1) * H_AST) * 2u;
        uint32_t bBase = sB + (uint32_t)((kt & 1) * H_BST) * 2u;
        #pragma unroll
        for (int ks = 0; ks < 4; ks++) {
            uint32_t a[4][4], bb[2][4];
            #pragma unroll
            for (int m = 0; m < 4; m++)
                ldsm4(a[m], aBase + aoff[m] + (uint32_t)(ks * 32));
            #pragma unroll
            for (int p = 0; p < 2; p++)
                ldsm4t(bb[p], bBase + boff[p] + (uint32_t)(ks * 16 * H_BLD * 2));
            #pragma unroll
            for (int m = 0; m < 4; m++) {
                #pragma unroll
                for (int p = 0; p < 2; p++) {
                    mma16(acc[m][p * 2],     a[m], bb[p][0], bb[p][1]);
                    mma16(acc[m][p * 2 + 1], a[m], bb[p][2], bb[p][3]);
                }
            }
        }
        __syncthreads();
    }

    #pragma unroll
    for (int m = 0; m < 4; m++) {
        int gr = bm + wm + m * 16 + gid;
        #pragma unroll
        for (int n = 0; n < 4; n++) {
            int gc = bn + wn + n * 8 + 2 * tig;
            if (gc < N) {
                float2 bi = *(const float2*)&bias[gc];
                float v0 = acc[m][n][0] + bi.x;
                float v1 = acc[m][n][1] + bi.y;
                float v2 = acc[m][n][2] + bi.x;
                float v3 = acc[m][n][3] + bi.y;
                if (EPI == EPI_SWIGLU) {
                    __half* C = (__half*)Cv;
                    int jcol = gc >> 1;
                    C[(size_t)gr * ldc + jcol]       = __float2half(fsilu(v0) * v1);
                    C[(size_t)(gr + 8) * ldc + jcol] = __float2half(fsilu(v2) * v3);
                } else {
                    if (EPI == EPI_RES) {
                        if (EH) {
                            const __half* ex = (const __half*)extra;
                            float2 e0 = __half22float2(*(const __half2*)&ex[(size_t)gr * ldc + gc]);
                            float2 e1 = __half22float2(*(const __half2*)&ex[(size_t)(gr + 8) * ldc + gc]);
                            v0 += e0.x; v1 += e0.y; v2 += e1.x; v3 += e1.y;
                        } else {
                            const float* ex = (const float*)extra;
                            float2 e0 = *(const float2*)&ex[(size_t)gr * ldc + gc];
                            float2 e1 = *(const float2*)&ex[(size_t)(gr + 8) * ldc + gc];
                            v0 += e0.x; v1 += e0.y; v2 += e1.x; v3 += e1.y;
                        }
                    }
                    if (OH) {
                        __half* C = (__half*)Cv;
                        *(uint32_t*)&C[(size_t)gr * ldc + gc]       = pkh2(v0, v1);
                        *(uint32_t*)&C[(size_t)(gr + 8) * ldc + gc] = pkh2(v2, v3);
                    } else {
                        float* C = (float*)Cv;
                        *(float2*)&C[(size_t)gr * ldc + gc]       = make_float2(v0, v1);
                        *(float2*)&C[(size_t)(gr + 8) * ldc + gc] = make_float2(v2, v3);
                    }
                }
            }
        }
    }
}

// ---------------- Flash attention: reverse kv, vote-skip, sorted grid --------
#define AKLD 72
#define AK_ST (128 * AKLD)
#define ASMEM ((4 * AK_ST) * 2)

__global__ void __launch_bounds__(256) attn_kernel(
    const __half* __restrict__ qkv, __half* __restrict__ out)
{
    extern __shared__ __align__(16) char smc[];
    __half* Ks = (__half*)smc;
    uint32_t sK = (uint32_t)__cvta_generic_to_shared(Ks);
    uint32_t sV = sK + (uint32_t)(2 * AK_ST) * 2u;

    int tid = threadIdx.x, lane = tid & 31, warp = tid >> 5;
    int gid = lane >> 2, tig = lane & 3;
    // sorted grid: heavy q-tiles (large qt) launch first across all heads/batches
    int bid = blockIdx.x;
    int qt = 15 - (bid >> 5);
    int hb = bid & 31;
    int h  = hb & 15, bb = hb >> 4;
    int q0 = qt * 128;
    int R  = warp * 16;
    const float LOG2E = 1.4426950408889634f;
    float qscale = 0.125f * LOG2E;
    float slope  = exp2f(-0.5f * (float)(h + 1)) * LOG2E;
    size_t base = (size_t)bb * TS * 3072;
    const __half* Qg = qkv + base + h * 64;
    const __half* Kg = Qg + 1024;
    const __half* Vg = Qg + 2048;

    int nsb = qt + 1;

    auto loadKV = [&](int sb) {
        int stg = sb & 1, k0 = sb * 128;
        #pragma unroll
        for (int j = 0; j < 4; j++) {
            int idx = tid + j * 256;
            int r = idx >> 3, c8 = (idx & 7) << 3;
            size_t go = (size_t)(k0 + r) * 3072 + c8;
            cp16(sK + (uint32_t)(stg * AK_ST + r * AKLD + c8) * 2u, Kg + go);
            cp16(sV + (uint32_t)(stg * AK_ST + r * AKLD + c8) * 2u, Vg + go);
        }
    };

    loadKV(nsb - 1);
    CP_COMMIT();

    uint32_t qa[4][4];
    {
        const __half* Qr1 = Qg + (size_t)(q0 + R + gid) * 3072;
        const __half* Qr2 = Qr1 + 8 * 3072;
        #pragma unroll
        for (int kt = 0; kt < 4; kt++) {
            int d0 = kt * 16 + 2 * tig;
            qa[kt][0] = pkh2(__half2float(Qr1[d0]) * qscale, __half2float(Qr1[d0 + 1]) * qscale);
            qa[kt][1] = pkh2(__half2float(Qr2[d0]) * qscale, __half2float(Qr2[d0 + 1]) * qscale);
            qa[kt][2] = pkh2(__half2float(Qr1[d0 + 8]) * qscale, __half2float(Qr1[d0 + 9]) * qscale);
            qa[kt][3] = pkh2(__half2float(Qr2[d0 + 8]) * qscale, __half2float(Qr2[d0 + 9]) * qscale);
        }
    }

    float oa[8][4];
    #pragma unroll
    for (int nt = 0; nt < 8; nt++)
        #pragma unroll
        for (int e = 0; e < 4; e++) oa[nt][e] = 0.0f;
    float m1 = -1e30f, m2 = -1e30f;
    float lp1 = 0.0f, lp2 = 0.0f;

    int qp1 = q0 + R + gid, qp2 = qp1 + 8;

    uint32_t koff = (uint32_t)(((((lane >> 4) << 3) + (lane & 7)) * AKLD + (((lane >> 3) & 1) << 3)) * 2);
    uint32_t voff = (uint32_t)(((lane & 15) * AKLD + (((lane >> 4) & 1) << 3)) * 2);

    for (int i = 0; i < nsb; i++) {
        int sb = nsb - 1 - i;
        if (sb > 0) loadKV(sb - 1);
        CP_COMMIT();
        CP_WAIT1();
        __syncthreads();
        uint32_t sKst = sK + (uint32_t)((sb & 1) * AK_ST) * 2u;
        uint32_t sVst = sV + (uint32_t)((sb & 1) * AK_ST) * 2u;

        #pragma unroll
        for (int hf = 0; hf < 2; hf++) {
            int half = 1 - hf;
            int k0 = sb * 128 + half * 64;
            uint32_t sKcur = sKst + (uint32_t)(half * 64 * AKLD) * 2u;
            uint32_t sVcur = sVst + (uint32_t)(half * 64 * AKLD) * 2u;
            int vis = q0 + R + 15 - k0;

            if (vis >= 0) {
                int ntmax = vis >> 3;
                ntmax = (ntmax >= 7) ? 8 : (ntmax + 1);
                float sacc[8][4];
                #pragma unroll
                for (int nt = 0; nt < 8; nt++)
                    #pragma unroll
                    for (int e = 0; e < 4; e++) sacc[nt][e] = 0.0f;
                #pragma unroll
                for (int ntp = 0; ntp < 8; ntp += 2) {
                    if (ntp < ntmax) {
                        #pragma unroll
                        for (int kt = 0; kt < 4; kt++) {
                            uint32_t bbr[4];
                            ldsm4(bbr, sKcur + koff + (uint32_t)((ntp * 8 * AKLD + kt * 16) * 2));
                            mma16(sacc[ntp],     qa[kt], bbr[0], bbr[1]);
                            mma16(sacc[ntp + 1], qa[kt], bbr[2], bbr[3]);
                        }
                    }
                }
                bool domask = (k0 + 63 > q0 + R);
                float mx1 = -1e30f, mx2 = -1e30f;
                #pragma unroll
                for (int nt = 0; nt < 8; nt++) {
                    if (nt >= ntmax) continue;
                    int kp0 = k0 + nt * 8 + tig * 2;
                    float cbA = -slope * (float)kp0;
                    float cbB = cbA - slope;
                    float s0 = sacc[nt][0] + cbA;
                    float s1 = sacc[nt][1] + cbB;
                    float s2 = sacc[nt][2] + cbA;
                    float s3 = sacc[nt][3] + cbB;
                    if (domask) {
                        if (kp0     > qp1) s0 = -1e30f;
                        if (kp0 + 1 > qp1) s1 = -1e30f;
                        if (kp0     > qp2) s2 = -1e30f;
                        if (kp0 + 1 > qp2) s3 = -1e30f;
                    }
                    sacc[nt][0] = s0; sacc[nt][1] = s1; sacc[nt][2] = s2; sacc[nt][3] = s3;
                    mx1 = fmaxf(mx1, fmaxf(s0, s1));
                    mx2 = fmaxf(mx2, fmaxf(s2, s3));
                }
                mx1 = fmaxf(mx1, __shfl_xor_sync(0xffffffffu, mx1, 1));
                mx1 = fmaxf(mx1, __shfl_xor_sync(0xffffffffu, mx1, 2));
                mx2 = fmaxf(mx2, __shfl_xor_sync(0xffffffffu, mx2, 1));
                mx2 = fmaxf(mx2, __shfl_xor_sync(0xffffffffu, mx2, 2));
                bool upd = (mx1 > m1) || (mx2 > m2);
                if (__any_sync(0xffffffffu, upd)) {
                    float mn1 = fmaxf(m1, mx1), mn2 = fmaxf(m2, mx2);
                    float f1 = ex2f(m1 - mn1), f2 = ex2f(m2 - mn2);
                    lp1 *= f1;  lp2 *= f2;
                    #pragma unroll
                    for (int nt = 0; nt < 8; nt++) {
                        oa[nt][0] *= f1; oa[nt][1] *= f1;
                        oa[nt][2] *= f2; oa[nt][3] *= f2;
                    }
                    m1 = mn1;  m2 = mn2;
                }
                #pragma unroll
                for (int nt = 0; nt < 8; nt++) {
                    if (nt >= ntmax) continue;
                    float p0 = ex2f(sacc[nt][0] - m1);
                    float p1 = ex2f(sacc[nt][1] - m1);
                    float p2 = ex2f(sacc[nt][2] - m2);
                    float p3 = ex2f(sacc[nt][3] - m2);
                    sacc[nt][0] = p0; sacc[nt][1] = p1; sacc[nt][2] = p2; sacc[nt][3] = p3;
                    lp1 += p0 + p1; lp2 += p2 + p3;
                }
                int jmax = (ntmax + 1) >> 1;
                #pragma unroll
                for (int j = 0; j < 4; j++) {
                    if (j >= jmax) continue;
                    uint32_t pa[4];
                    pa[0] = pkh2(sacc[2*j][0], sacc[2*j][1]);
                    pa[1] = pkh2(sacc[2*j][2], sacc[2*j][3]);
                    if (2*j + 1 < ntmax) {
                        pa[2] = pkh2(sacc[2*j+1][0], sacc[2*j+1][1]);
                        pa[3] = pkh2(sacc[2*j+1][2], sacc[2*j+1][3]);
                    } else { pa[2] = 0u; pa[3] = 0u; }
                    uint32_t rowa = sVcur + voff + (uint32_t)(j * 16 * AKLD) * 2u;
                    #pragma unroll
                    for (int nt = 0; nt < 8; nt += 2) {
                        uint32_t bbr[4];
                        ldsm4t(bbr, rowa + (uint32_t)(nt * 8) * 2u);
                        mma16(oa[nt],     pa, bbr[0], bbr[1]);
                        mma16(oa[nt + 1], pa, bbr[2], bbr[3]);
                    }
                }
            }
        }
        __syncthreads();
    }

    lp1 += __shfl_xor_sync(0xffffffffu, lp1, 1);
    lp1 += __shfl_xor_sync(0xffffffffu, lp1, 2);
    lp2 += __shfl_xor_sync(0xffffffffu, lp2, 1);
    lp2 += __shfl_xor_sync(0xffffffffu, lp2, 2);
    float il1 = rcpf(lp1), il2 = rcpf(lp2);
    __half* Or1 = out + (size_t)(bb * TS + q0 + R + gid) * N_EMBD + h * 64;
    __half* Or2 = Or1 + 8 * N_EMBD;
    #pragma unroll
    for (int nt = 0; nt < 8; nt++) {
        *(uint32_t*)&Or1[nt * 8 + 2 * tig] = pkh2(oa[nt][0] * il1, oa[nt][1] * il1);
        *(uint32_t*)&Or2[nt * 8 + 2 * tig] = pkh2(oa[nt][2] * il2, oa[nt][3] * il2);
    }
}

// ---------------- launch -----------------------------------------------------
extern "C" void kernel_launch(void* const* d_in, const int* in_sizes, int n_in,
                              void* d_out, int out_size)
{
    (void)in_sizes; (void)n_in; (void)out_size;
    const float* x      = (const float*)d_in[0];
    const float* ln1_g  = (const float*)d_in[1];
    const float* ln1_b  = (const float*)d_in[2];
    const float* qkv_w  = (const float*)d_in[3];
    const float* qkv_b  = (const float*)d_in[4];
    const float* proj_w = (const float*)d_in[5];
    const float* proj_b = (const float*)d_in[6];
    const float* ln2_g  = (const float*)d_in[7];
    const float* ln2_b  = (const float*)d_in[8];
    const float* gate_w = (const float*)d_in[9];
    const float* gate_b = (const float*)d_in[10];
    const float* up_w   = (const float*)d_in[11];
    const float* up_b   = (const float*)d_in[12];
    const float* down_w = (const float*)d_in[13];
    const float* down_b = (const float*)d_in[14];
    float* out = (float*)d_out;

    __half *hh, *qkvh, *atth, *ffh, *x2h, *qkvw, *projw, *downw, *wcomb;
    float *bcomb;
    cudaGetSymbolAddress((void**)&hh,    g_hh);
    cudaGetSymbolAddress((void**)&qkvh,  g_qkvh);
    cudaGetSymbolAddress((void**)&atth,  g_atth);
    cudaGetSymbolAddress((void**)&ffh,   g_ffh);
    cudaGetSymbolAddress((void**)&x2h,   g_x2h);
    cudaGetSymbolAddress((void**)&qkvw,  g_qkvw);
    cudaGetSymbolAddress((void**)&projw, g_projw);
    cudaGetSymbolAddress((void**)&downw, g_downw);
    cudaGetSymbolAddress((void**)&wcomb, g_wcomb);
    cudaGetSymbolAddress((void**)&bcomb, g_bcomb);

    cudaFuncSetAttribute(gemm_fp16<EPI_BIAS,  1,0>, cudaFuncAttributeMaxDynamicSharedMemorySize, GSMEM);
    cudaFuncSetAttribute(gemm_fp16<EPI_RES,   1,0>, cudaFuncAttributeMaxDynamicSharedMemorySize, GSMEM);
    cudaFuncSetAttribute(gemm_fp16<EPI_RES,   0,1>, cudaFuncAttributeMaxDynamicSharedMemorySize, GSMEM);
    cudaFuncSetAttribute(gemm_fp16<EPI_SWIGLU,1,0>, cudaFuncAttributeMaxDynamicSharedMemorySize, GSMEM);
    cudaFuncSetAttribute(attn_kernel, cudaFuncAttributeMaxDynamicSharedMemorySize, ASMEM);

    // 0) all weight conversions in ONE launch
    convall_kernel<<<CB_ALL, 256>>>(qkv_w, proj_w, down_w, gate_w, up_w, gate_b, up_b,
                                    qkvw, projw, downw, wcomb, bcomb);

    // 1) LN1 (fp32 in)
    ln_kernel<0><<<BT, 256>>>(x, ln1_g, ln1_b, hh);
    // 2) qkv
    {
        dim3 g(3 * N_EMBD / 128, BT / 128);
        gemm_fp16<EPI_BIAS,1,0><<<g, 256, GSMEM>>>(hh, qkvw, qkv_b, nullptr, qkvh,
                                                   3 * N_EMBD, N_EMBD, N_EMBD, 3 * N_EMBD, 3 * N_EMBD);
    }
    // 3) attention (flattened, heavy-first sorted grid)
    attn_kernel<<<512, 256, ASMEM>>>(qkvh, atth);
    // 4) x2 = att @ proj_w + b + x   (half out)
    {
        dim3 g(N_EMBD / 128, BT / 128);
        gemm_fp16<EPI_RES,1,0><<<g, 256, GSMEM>>>(atth, projw, proj_b, x, x2h,
                                                  N_EMBD, N_EMBD, N_EMBD, N_EMBD, N_EMBD);
    }
    // 5) LN2 (fp16 in)
    ln_kernel<1><<<BT, 256>>>(x2h, ln2_g, ln2_b, hh);
    // 6+7) ff = silu(h@gate_w+bg) * (h@up_w+bu)
    {
        dim3 g(IW_LD / 128, BT / 128);
        gemm_fp16<EPI_SWIGLU,1,0><<<g, 256, GSMEM>>>(hh, wcomb, bcomb, nullptr, ffh,
                                                     2 * HID, N_EMBD, N_EMBD, IW_LD, FF_LD);
    }
    // 8) out = ff @ down_w + b + x2  (residual half, out fp32)
    {
        dim3 g(N_EMBD / 128, BT / 128);
        gemm_fp16<EPI_RES,0,1><<<g, 256, GSMEM>>>(ffh, downw, down_b, x2h, out,
                                                  N_EMBD, HID, FF_LD, N_EMBD, N_EMBD);
    }
}